// round 15
// baseline (speedup 1.0000x reference)
#include <cuda_runtime.h>
#include <cuda_bf16.h>
#include <cuda_fp16.h>
#include <math.h>

#define NFEAT   256
#define NHID    64
#define NCLASS  16
#define MAXN    50000
#define MAXE    1600000

// ---------------------------------------------------------------------------
// Scratch (allocation-free device globals)
// ---------------------------------------------------------------------------
__device__ __align__(16) __half g_S1h[MAXN * NHID];    // x @ W1      (fp16)
__device__ __align__(16) float  g_H  [MAXN * NHID];    // spmm1 + b1  (fp32)
__device__ __align__(16) __half g_S2h[MAXN * NCLASS];  // relu(H)@W2  (fp16)

__device__ __align__(16) int  g_cnt[MAXN];      // in-degree per dst
__device__ __align__(16) int  g_off[MAXN];      // CSR row offsets
__device__ __align__(16) int  g_rank[MAXE];     // per-edge rank within dst bucket
__device__ int  g_state[128];                   // decoupled-lookback state
__device__ __align__(16) int2 g_csr[MAXE];      // packed (src, w-bits), by dst

// ---------------------------------------------------------------------------
// GEMM1 via tf32 tensor cores: S1[N,64] = x[N,256] @ W1[256,64], fp16 output
// ---------------------------------------------------------------------------
__device__ __forceinline__ unsigned f2tf32(float f) {
    unsigned u;
    asm("cvt.rna.tf32.f32 %0, %1;" : "=r"(u) : "f"(f));
    return u;
}

__global__ void __launch_bounds__(256) gemm1_tf32_kernel(
    const float* __restrict__ x, const float* __restrict__ W1, int n_nodes)
{
    __shared__ unsigned xs[64][36];
    __shared__ unsigned ws[32][72];

    const int tid = threadIdx.x;
    const int w   = tid >> 5;
    const int lane = tid & 31;
    const int mw = w >> 1;
    const int nw = w & 1;
    const int lr = lane >> 2;
    const int lc = lane & 3;
    const int rowBase = blockIdx.x * 64;

    float acc[4][4];
#pragma unroll
    for (int i = 0; i < 4; i++)
#pragma unroll
        for (int j = 0; j < 4; j++) acc[i][j] = 0.f;

#pragma unroll 1
    for (int k0 = 0; k0 < NFEAT; k0 += 32) {
#pragma unroll
        for (int j = 0; j < 2; j++) {
            int s = tid * 2 + j;
            int r = s >> 3;
            int c4 = s & 7;
            float4 v = make_float4(0.f, 0.f, 0.f, 0.f);
            int grow = rowBase + r;
            if (grow < n_nodes)
                v = *reinterpret_cast<const float4*>(&x[grow * NFEAT + k0 + c4 * 4]);
            xs[r][c4 * 4 + 0] = f2tf32(v.x);
            xs[r][c4 * 4 + 1] = f2tf32(v.y);
            xs[r][c4 * 4 + 2] = f2tf32(v.z);
            xs[r][c4 * 4 + 3] = f2tf32(v.w);
        }
#pragma unroll
        for (int j = 0; j < 2; j++) {
            int s = tid * 2 + j;
            int kk = s >> 4;
            int c4 = s & 15;
            float4 v = *reinterpret_cast<const float4*>(&W1[(k0 + kk) * NHID + c4 * 4]);
            ws[kk][c4 * 4 + 0] = f2tf32(v.x);
            ws[kk][c4 * 4 + 1] = f2tf32(v.y);
            ws[kk][c4 * 4 + 2] = f2tf32(v.z);
            ws[kk][c4 * 4 + 3] = f2tf32(v.w);
        }
        __syncthreads();

#pragma unroll
        for (int k8 = 0; k8 < 32; k8 += 8) {
            unsigned a0 = xs[16 * mw + lr    ][k8 + lc    ];
            unsigned a1 = xs[16 * mw + lr + 8][k8 + lc    ];
            unsigned a2 = xs[16 * mw + lr    ][k8 + lc + 4];
            unsigned a3 = xs[16 * mw + lr + 8][k8 + lc + 4];
#pragma unroll
            for (int nt = 0; nt < 4; nt++) {
                int ncol = 32 * nw + 8 * nt + lr;
                unsigned b0 = ws[k8 + lc    ][ncol];
                unsigned b1 = ws[k8 + lc + 4][ncol];
                asm volatile(
                    "mma.sync.aligned.m16n8k8.row.col.f32.tf32.tf32.f32 "
                    "{%0,%1,%2,%3}, {%4,%5,%6,%7}, {%8,%9}, {%0,%1,%2,%3};"
                    : "+f"(acc[nt][0]), "+f"(acc[nt][1]),
                      "+f"(acc[nt][2]), "+f"(acc[nt][3])
                    : "r"(a0), "r"(a1), "r"(a2), "r"(a3), "r"(b0), "r"(b1));
            }
        }
        __syncthreads();
    }

    int r0 = rowBase + 16 * mw + lr;
#pragma unroll
    for (int nt = 0; nt < 4; nt++) {
        int c = 32 * nw + 8 * nt + 2 * lc;
        if (r0 < n_nodes)
            *reinterpret_cast<__half2*>(&g_S1h[r0 * NHID + c]) =
                __floats2half2_rn(acc[nt][0], acc[nt][1]);
        if (r0 + 8 < n_nodes)
            *reinterpret_cast<__half2*>(&g_S1h[(r0 + 8) * NHID + c]) =
                __floats2half2_rn(acc[nt][2], acc[nt][3]);
    }
}

// ---------------------------------------------------------------------------
// CSR build: zero -> histogram(+rank, x4) -> one-pass scan -> scatter (x4)
// (exact R12 configuration — measured best)
// ---------------------------------------------------------------------------
__global__ void zero_cnt_kernel(int n4)   // n4 = ceil(n/4)
{
    int i = blockIdx.x * blockDim.x + threadIdx.x;
    if (i < n4)
        *reinterpret_cast<int4*>(&g_cnt[i * 4]) = make_int4(0, 0, 0, 0);
    if (i < 128) g_state[i] = 0;
}

__global__ void hist_rank_kernel(const int* __restrict__ dst, int n_edges)
{
    int t = blockIdx.x * blockDim.x + threadIdx.x;
    int e = t * 4;
    if (e + 3 < n_edges) {
        int4 d = *reinterpret_cast<const int4*>(&dst[e]);
        int r0 = atomicAdd(&g_cnt[d.x], 1);
        int r1 = atomicAdd(&g_cnt[d.y], 1);
        int r2 = atomicAdd(&g_cnt[d.z], 1);
        int r3 = atomicAdd(&g_cnt[d.w], 1);
        *reinterpret_cast<int4*>(&g_rank[e]) = make_int4(r0, r1, r2, r3);
    } else {
        for (; e < n_edges; e++)
            g_rank[e] = atomicAdd(&g_cnt[dst[e]], 1);
    }
}

__global__ void __launch_bounds__(512) scan_onepass_kernel(int n)
{
    __shared__ int wsum[16];
    __shared__ int s_prefix;
    const int b = blockIdx.x;
    const int i = b * 512 + threadIdx.x;
    const int lane = threadIdx.x & 31, wid = threadIdx.x >> 5;

    int v = (i < n) ? g_cnt[i] : 0;
    int x = v;
#pragma unroll
    for (int o = 1; o < 32; o <<= 1) {
        int t = __shfl_up_sync(0xffffffffu, x, o);
        if (lane >= o) x += t;
    }
    if (lane == 31) wsum[wid] = x;
    __syncthreads();
    if (wid == 0) {
        int s = (lane < 16) ? wsum[lane] : 0;
#pragma unroll
        for (int o = 1; o < 16; o <<= 1) {
            int t = __shfl_up_sync(0xffffffffu, s, o);
            if (lane >= o) s += t;
        }
        if (lane < 16) wsum[lane] = s;
    }
    __syncthreads();
    const int base  = (wid > 0) ? wsum[wid - 1] : 0;
    const int total = wsum[15];

    if (threadIdx.x == 0)
        atomicExch(&g_state[b], (total << 2) | (b == 0 ? 2 : 1));

    if (wid == 0) {
        int prefix = 0;
        if (b > 0) {
            int j = b - 1;
            while (true) {
                int idx = j - lane;
                int s = (idx >= 0) ? atomicAdd(&g_state[idx], 0) : 2;
                if (__all_sync(0xffffffffu, (s & 3) != 0)) {
                    unsigned pm = __ballot_sync(0xffffffffu, (s & 3) == 2);
                    int cut = pm ? (__ffs(pm) - 1) : 32;
                    int val = (lane <= cut) ? (s >> 2) : 0;
#pragma unroll
                    for (int o = 16; o; o >>= 1)
                        val += __shfl_xor_sync(0xffffffffu, val, o);
                    prefix += val;
                    if (cut < 32) break;
                    j -= 32;
                }
            }
            if (lane == 0)
                atomicExch(&g_state[b], ((prefix + total) << 2) | 2);
        }
        if (lane == 0) s_prefix = prefix;
    }
    __syncthreads();

    int off = s_prefix + base + x - v;
    if (i < n) g_off[i] = off;
}

__global__ void scatter_kernel(
    const int* __restrict__ src, const int* __restrict__ dst,
    const float* __restrict__ ew, int n_edges)
{
    int t = blockIdx.x * blockDim.x + threadIdx.x;
    int e = t * 4;
    if (e + 3 < n_edges) {
        int4   d = *reinterpret_cast<const int4*>(&dst[e]);
        int4   s = *reinterpret_cast<const int4*>(&src[e]);
        int4   r = *reinterpret_cast<const int4*>(&g_rank[e]);
        float4 w = *reinterpret_cast<const float4*>(&ew[e]);
        int o0 = g_off[d.x], o1 = g_off[d.y], o2 = g_off[d.z], o3 = g_off[d.w];
        g_csr[o0 + r.x] = make_int2(s.x, __float_as_int(w.x));
        g_csr[o1 + r.y] = make_int2(s.y, __float_as_int(w.y));
        g_csr[o2 + r.z] = make_int2(s.z, __float_as_int(w.z));
        g_csr[o3 + r.w] = make_int2(s.w, __float_as_int(w.w));
    } else {
        for (; e < n_edges; e++) {
            int d = dst[e];
            g_csr[g_off[d] + g_rank[e]] = make_int2(src[e], __float_as_int(ew[e]));
        }
    }
}

// ---------------------------------------------------------------------------
// SpMM1 (pull, 2 warps per dst): H[d] = b1 + sum_e w_e * S1[src_e]
// Each dst's edge range is split across a warp pair; partials combined in smem.
// Halves the per-row serial csr->gather chain. Block = 256 thr = 4 dsts.
// ---------------------------------------------------------------------------
__global__ void __launch_bounds__(256) spmm1_pull_kernel(
    const float* __restrict__ b1, int n_nodes)
{
    __shared__ float2 part[4][32];

    const int tid  = threadIdx.x;
    const int lane = tid & 31;
    const int pair = tid >> 6;          // 0..3: which dst in block
    const int ws   = (tid >> 5) & 1;    // 0/1: which half of edge list
    const int d    = blockIdx.x * 4 + pair;
    const bool valid = (d < n_nodes);

    float2 acc = make_float2(0.f, 0.f);
    int j = 0, end = 0;
    if (valid) {
        int rbeg = g_off[d];
        int cnt  = g_cnt[d];
        int half = (cnt + 1) >> 1;
        j   = rbeg + (ws ? half : 0);
        end = rbeg + (ws ? cnt  : half);
    }

    if ((j & 1) && j < end) {
        int2 e = g_csr[j];
        float2 v = __half22float2(*reinterpret_cast<const __half2*>(&g_S1h[e.x * NHID + 2 * lane]));
        float wt = __int_as_float(e.y);
        acc.x = fmaf(wt, v.x, acc.x); acc.y = fmaf(wt, v.y, acc.y);
        j++;
    }
    const int4* csr4 = reinterpret_cast<const int4*>(g_csr);
    for (; j + 7 < end; j += 8) {
        int h = j >> 1;
        int4 p0 = csr4[h + 0], p1 = csr4[h + 1], p2 = csr4[h + 2], p3 = csr4[h + 3];
        float2 v0 = __half22float2(*reinterpret_cast<const __half2*>(&g_S1h[p0.x * NHID + 2 * lane]));
        float2 v1 = __half22float2(*reinterpret_cast<const __half2*>(&g_S1h[p0.z * NHID + 2 * lane]));
        float2 v2 = __half22float2(*reinterpret_cast<const __half2*>(&g_S1h[p1.x * NHID + 2 * lane]));
        float2 v3 = __half22float2(*reinterpret_cast<const __half2*>(&g_S1h[p1.z * NHID + 2 * lane]));
        float2 v4 = __half22float2(*reinterpret_cast<const __half2*>(&g_S1h[p2.x * NHID + 2 * lane]));
        float2 v5 = __half22float2(*reinterpret_cast<const __half2*>(&g_S1h[p2.z * NHID + 2 * lane]));
        float2 v6 = __half22float2(*reinterpret_cast<const __half2*>(&g_S1h[p3.x * NHID + 2 * lane]));
        float2 v7 = __half22float2(*reinterpret_cast<const __half2*>(&g_S1h[p3.z * NHID + 2 * lane]));
        float w0 = __int_as_float(p0.y), w1 = __int_as_float(p0.w);
        float w2 = __int_as_float(p1.y), w3 = __int_as_float(p1.w);
        float w4 = __int_as_float(p2.y), w5 = __int_as_float(p2.w);
        float w6 = __int_as_float(p3.y), w7 = __int_as_float(p3.w);
        acc.x = fmaf(w0, v0.x, acc.x); acc.y = fmaf(w0, v0.y, acc.y);
        acc.x = fmaf(w1, v1.x, acc.x); acc.y = fmaf(w1, v1.y, acc.y);
        acc.x = fmaf(w2, v2.x, acc.x); acc.y = fmaf(w2, v2.y, acc.y);
        acc.x = fmaf(w3, v3.x, acc.x); acc.y = fmaf(w3, v3.y, acc.y);
        acc.x = fmaf(w4, v4.x, acc.x); acc.y = fmaf(w4, v4.y, acc.y);
        acc.x = fmaf(w5, v5.x, acc.x); acc.y = fmaf(w5, v5.y, acc.y);
        acc.x = fmaf(w6, v6.x, acc.x); acc.y = fmaf(w6, v6.y, acc.y);
        acc.x = fmaf(w7, v7.x, acc.x); acc.y = fmaf(w7, v7.y, acc.y);
    }
    for (; j + 1 < end; j += 2) {
        int4 p = csr4[j >> 1];
        float2 v0 = __half22float2(*reinterpret_cast<const __half2*>(&g_S1h[p.x * NHID + 2 * lane]));
        float2 v1 = __half22float2(*reinterpret_cast<const __half2*>(&g_S1h[p.z * NHID + 2 * lane]));
        float w0 = __int_as_float(p.y), w1 = __int_as_float(p.w);
        acc.x = fmaf(w0, v0.x, acc.x); acc.y = fmaf(w0, v0.y, acc.y);
        acc.x = fmaf(w1, v1.x, acc.x); acc.y = fmaf(w1, v1.y, acc.y);
    }
    if (j < end) {
        int2 e = g_csr[j];
        float2 v = __half22float2(*reinterpret_cast<const __half2*>(&g_S1h[e.x * NHID + 2 * lane]));
        float wt = __int_as_float(e.y);
        acc.x = fmaf(wt, v.x, acc.x); acc.y = fmaf(wt, v.y, acc.y);
    }

    // Combine warp pair: ws=1 publishes, ws=0 adds bias + stores.
    if (ws == 1) part[pair][lane] = acc;
    __syncthreads();
    if (ws == 0 && valid) {
        float2 o = part[pair][lane];
        float2 b = *reinterpret_cast<const float2*>(&b1[2 * lane]);
        *reinterpret_cast<float2*>(&g_H[d * NHID + 2 * lane]) =
            make_float2(acc.x + o.x + b.x, acc.y + o.y + b.y);
    }
}

// ---------------------------------------------------------------------------
// GEMM2 fused ReLU: S2[N,16] = relu(H)[N,64] @ W2[64,16], fp16 output (R12)
// ---------------------------------------------------------------------------
__global__ void __launch_bounds__(256) gemm2_kernel(
    const float* __restrict__ W2, int n_nodes)
{
    __shared__ float hs[128][68];
    __shared__ float ws2[64][16];

    const int tid = threadIdx.x;
    const int tx = tid & 3;
    const int ty = tid >> 2;
    const int rowBase = blockIdx.x * 128;

#pragma unroll
    for (int j = 0; j < 8; j++) {
        int s = tid + j * 256;
        int r = s >> 4;
        int c4 = s & 15;
        float4 v = make_float4(0.f, 0.f, 0.f, 0.f);
        int grow = rowBase + r;
        if (grow < n_nodes)
            v = *reinterpret_cast<const float4*>(&g_H[grow * NHID + c4 * 4]);
        v.x = fmaxf(v.x, 0.f); v.y = fmaxf(v.y, 0.f);
        v.z = fmaxf(v.z, 0.f); v.w = fmaxf(v.w, 0.f);
        *reinterpret_cast<float4*>(&hs[r][c4 * 4]) = v;
    }
    {
        int kk = tid >> 2;
        int c4 = tid & 3;
        float4 v = *reinterpret_cast<const float4*>(&W2[kk * NCLASS + c4 * 4]);
        *reinterpret_cast<float4*>(&ws2[kk][c4 * 4]) = v;
    }
    __syncthreads();

    float acc0[4] = {0.f, 0.f, 0.f, 0.f};
    float acc1[4] = {0.f, 0.f, 0.f, 0.f};
#pragma unroll
    for (int kk = 0; kk < NHID; kk++) {
        float a0 = hs[ty][kk];
        float a1 = hs[ty + 64][kk];
        float4 w = *reinterpret_cast<const float4*>(&ws2[kk][4 * tx]);
        acc0[0] = fmaf(a0, w.x, acc0[0]); acc0[1] = fmaf(a0, w.y, acc0[1]);
        acc0[2] = fmaf(a0, w.z, acc0[2]); acc0[3] = fmaf(a0, w.w, acc0[3]);
        acc1[0] = fmaf(a1, w.x, acc1[0]); acc1[1] = fmaf(a1, w.y, acc1[1]);
        acc1[2] = fmaf(a1, w.z, acc1[2]); acc1[3] = fmaf(a1, w.w, acc1[3]);
    }

    int r0 = rowBase + ty, r1 = rowBase + ty + 64;
    if (r0 < n_nodes) {
        __half2 h2[2] = { __floats2half2_rn(acc0[0], acc0[1]),
                          __floats2half2_rn(acc0[2], acc0[3]) };
        *reinterpret_cast<uint2*>(&g_S2h[r0 * NCLASS + 4 * tx]) =
            *reinterpret_cast<const uint2*>(h2);
    }
    if (r1 < n_nodes) {
        __half2 h2[2] = { __floats2half2_rn(acc1[0], acc1[1]),
                          __floats2half2_rn(acc1[2], acc1[3]) };
        *reinterpret_cast<uint2*>(&g_S2h[r1 * NCLASS + 4 * tx]) =
            *reinterpret_cast<const uint2*>(h2);
    }
}

// ---------------------------------------------------------------------------
// SpMM2 (pull) + bias + log_softmax fused (R12 exact: 4-edge unroll)
// ---------------------------------------------------------------------------
__global__ void __launch_bounds__(256) spmm2_lsm_kernel(
    const float* __restrict__ b2, float* __restrict__ out, int n_nodes)
{
    int lane16 = threadIdx.x & 15;
    int d = blockIdx.x * 16 + (threadIdx.x >> 4);
    if (d >= n_nodes) return;

    float acc = b2[lane16];
    int beg = g_off[d];
    int end = beg + g_cnt[d];
    int j = beg;

    if ((j & 1) && j < end) {
        int2 e = g_csr[j];
        acc = fmaf(__int_as_float(e.y), __half2float(g_S2h[e.x * NCLASS + lane16]), acc);
        j++;
    }
    const int4* csr4 = reinterpret_cast<const int4*>(g_csr);
    for (; j + 3 < end; j += 4) {
        int h = j >> 1;
        int4 p0 = csr4[h], p1 = csr4[h + 1];
        float v0 = __half2float(g_S2h[p0.x * NCLASS + lane16]);
        float v1 = __half2float(g_S2h[p0.z * NCLASS + lane16]);
        float v2 = __half2float(g_S2h[p1.x * NCLASS + lane16]);
        float v3 = __half2float(g_S2h[p1.z * NCLASS + lane16]);
        acc = fmaf(__int_as_float(p0.y), v0, acc);
        acc = fmaf(__int_as_float(p0.w), v1, acc);
        acc = fmaf(__int_as_float(p1.y), v2, acc);
        acc = fmaf(__int_as_float(p1.w), v3, acc);
    }
    for (; j < end; j++) {
        int2 e = g_csr[j];
        acc = fmaf(__int_as_float(e.y), __half2float(g_S2h[e.x * NCLASS + lane16]), acc);
    }

    float m = acc;
#pragma unroll
    for (int o = 8; o >= 1; o >>= 1)
        m = fmaxf(m, __shfl_xor_sync(0xffffffffu, m, o, 16));
    float ssum = expf(acc - m);
#pragma unroll
    for (int o = 8; o >= 1; o >>= 1)
        ssum += __shfl_xor_sync(0xffffffffu, ssum, o, 16);
    out[d * NCLASS + lane16] = acc - m - logf(ssum);
}

// ---------------------------------------------------------------------------
// Launch.  Inputs: x, W1, b1, W2, b2, edge_src, edge_dst, edge_weight
// gemm1 forks onto a side stream, overlapping the CSR build; joins before spmm1.
// ---------------------------------------------------------------------------
extern "C" void kernel_launch(void* const* d_in, const int* in_sizes, int n_in,
                              void* d_out, int out_size)
{
    const float* x    = (const float*)d_in[0];
    const float* W1   = (const float*)d_in[1];
    const float* b1   = (const float*)d_in[2];
    const float* W2   = (const float*)d_in[3];
    const float* b2   = (const float*)d_in[4];
    const int*   esrc = (const int*)d_in[5];
    const int*   edst = (const int*)d_in[6];
    const float* ew   = (const float*)d_in[7];

    int n_nodes = in_sizes[0] / NFEAT;
    int n_edges = in_sizes[5];
    int nb  = (n_nodes + 511) / 512;
    int n4e = (n_edges + 3) / 4;
    int n4n = (n_nodes + 3) / 4;

    cudaStream_t s1;
    cudaEvent_t evFork, evJoin;
    cudaStreamCreateWithFlags(&s1, cudaStreamNonBlocking);
    cudaEventCreateWithFlags(&evFork, cudaEventDisableTiming);
    cudaEventCreateWithFlags(&evJoin, cudaEventDisableTiming);

    cudaEventRecord(evFork, 0);
    cudaStreamWaitEvent(s1, evFork, 0);
    gemm1_tf32_kernel<<<(n_nodes + 63) / 64, 256, 0, s1>>>(x, W1, n_nodes);
    cudaEventRecord(evJoin, s1);

    // CSR-by-dst build (default stream) — exact R12 config
    zero_cnt_kernel<<<(n4n + 255) / 256, 256>>>(n4n);
    hist_rank_kernel<<<(n4e + 255) / 256, 256>>>(edst, n_edges);
    scan_onepass_kernel<<<nb, 512>>>(n_nodes);
    scatter_kernel<<<(n4e + 255) / 256, 256>>>(esrc, edst, ew, n_edges);

    cudaStreamWaitEvent(0, evJoin, 0);

    // Layer 1 aggregate: 2 warps per dst (4 dsts per 256-thread block)
    spmm1_pull_kernel<<<(n_nodes + 3) / 4, 256>>>(b1, n_nodes);
    gemm2_kernel<<<(n_nodes + 127) / 128, 256>>>(W2, n_nodes);
    spmm2_lsm_kernel<<<(n_nodes + 15) / 16, 256>>>(b2, (float*)d_out, n_nodes);

    cudaEventDestroy(evFork);
    cudaEventDestroy(evJoin);
    cudaStreamDestroy(s1);
}

// round 16
// speedup vs baseline: 1.0575x; 1.0575x over previous
#include <cuda_runtime.h>
#include <cuda_bf16.h>
#include <cuda_fp16.h>
#include <math.h>

#define NFEAT   256
#define NHID    64
#define NCLASS  16
#define MAXN    50000
#define MAXE    1600000

// ---------------------------------------------------------------------------
// Scratch (allocation-free device globals)
// ---------------------------------------------------------------------------
__device__ __align__(16) __half g_S1h[MAXN * NHID];    // x @ W1      (fp16)
__device__ __align__(16) float  g_H  [MAXN * NHID];    // spmm1 + b1  (fp32)
__device__ __align__(16) __half g_S2h[MAXN * NCLASS];  // relu(H)@W2  (fp16)

__device__ __align__(16) int  g_cnt[MAXN];      // in-degree per dst
__device__ __align__(16) int  g_off[MAXN];      // CSR row offsets
__device__ __align__(16) int  g_rank[MAXE];     // per-edge rank within dst bucket
__device__ int  g_state[128];                   // decoupled-lookback state
__device__ __align__(16) int2 g_csr[MAXE];      // packed (src, w-bits), by dst

// ---------------------------------------------------------------------------
// GEMM1 via tf32 tensor cores: S1[N,64] = x[N,256] @ W1[256,64], fp16 output
// ---------------------------------------------------------------------------
__device__ __forceinline__ unsigned f2tf32(float f) {
    unsigned u;
    asm("cvt.rna.tf32.f32 %0, %1;" : "=r"(u) : "f"(f));
    return u;
}

__global__ void __launch_bounds__(256) gemm1_tf32_kernel(
    const float* __restrict__ x, const float* __restrict__ W1, int n_nodes)
{
    __shared__ unsigned xs[64][36];
    __shared__ unsigned ws[32][72];

    const int tid = threadIdx.x;
    const int w   = tid >> 5;
    const int lane = tid & 31;
    const int mw = w >> 1;
    const int nw = w & 1;
    const int lr = lane >> 2;
    const int lc = lane & 3;
    const int rowBase = blockIdx.x * 64;

    float acc[4][4];
#pragma unroll
    for (int i = 0; i < 4; i++)
#pragma unroll
        for (int j = 0; j < 4; j++) acc[i][j] = 0.f;

#pragma unroll 1
    for (int k0 = 0; k0 < NFEAT; k0 += 32) {
#pragma unroll
        for (int j = 0; j < 2; j++) {
            int s = tid * 2 + j;
            int r = s >> 3;
            int c4 = s & 7;
            float4 v = make_float4(0.f, 0.f, 0.f, 0.f);
            int grow = rowBase + r;
            if (grow < n_nodes)
                v = *reinterpret_cast<const float4*>(&x[grow * NFEAT + k0 + c4 * 4]);
            xs[r][c4 * 4 + 0] = f2tf32(v.x);
            xs[r][c4 * 4 + 1] = f2tf32(v.y);
            xs[r][c4 * 4 + 2] = f2tf32(v.z);
            xs[r][c4 * 4 + 3] = f2tf32(v.w);
        }
#pragma unroll
        for (int j = 0; j < 2; j++) {
            int s = tid * 2 + j;
            int kk = s >> 4;
            int c4 = s & 15;
            float4 v = *reinterpret_cast<const float4*>(&W1[(k0 + kk) * NHID + c4 * 4]);
            ws[kk][c4 * 4 + 0] = f2tf32(v.x);
            ws[kk][c4 * 4 + 1] = f2tf32(v.y);
            ws[kk][c4 * 4 + 2] = f2tf32(v.z);
            ws[kk][c4 * 4 + 3] = f2tf32(v.w);
        }
        __syncthreads();

#pragma unroll
        for (int k8 = 0; k8 < 32; k8 += 8) {
            unsigned a0 = xs[16 * mw + lr    ][k8 + lc    ];
            unsigned a1 = xs[16 * mw + lr + 8][k8 + lc    ];
            unsigned a2 = xs[16 * mw + lr    ][k8 + lc + 4];
            unsigned a3 = xs[16 * mw + lr + 8][k8 + lc + 4];
#pragma unroll
            for (int nt = 0; nt < 4; nt++) {
                int ncol = 32 * nw + 8 * nt + lr;
                unsigned b0 = ws[k8 + lc    ][ncol];
                unsigned b1 = ws[k8 + lc + 4][ncol];
                asm volatile(
                    "mma.sync.aligned.m16n8k8.row.col.f32.tf32.tf32.f32 "
                    "{%0,%1,%2,%3}, {%4,%5,%6,%7}, {%8,%9}, {%0,%1,%2,%3};"
                    : "+f"(acc[nt][0]), "+f"(acc[nt][1]),
                      "+f"(acc[nt][2]), "+f"(acc[nt][3])
                    : "r"(a0), "r"(a1), "r"(a2), "r"(a3), "r"(b0), "r"(b1));
            }
        }
        __syncthreads();
    }

    int r0 = rowBase + 16 * mw + lr;
#pragma unroll
    for (int nt = 0; nt < 4; nt++) {
        int c = 32 * nw + 8 * nt + 2 * lc;
        if (r0 < n_nodes)
            *reinterpret_cast<__half2*>(&g_S1h[r0 * NHID + c]) =
                __floats2half2_rn(acc[nt][0], acc[nt][1]);
        if (r0 + 8 < n_nodes)
            *reinterpret_cast<__half2*>(&g_S1h[(r0 + 8) * NHID + c]) =
                __floats2half2_rn(acc[nt][2], acc[nt][3]);
    }
}

// ---------------------------------------------------------------------------
// CSR build: zero -> histogram(+rank, x4) -> one-pass scan -> scatter (x4)
// (exact R12 configuration — measured best)
// ---------------------------------------------------------------------------
__global__ void zero_cnt_kernel(int n4)   // n4 = ceil(n/4)
{
    int i = blockIdx.x * blockDim.x + threadIdx.x;
    if (i < n4)
        *reinterpret_cast<int4*>(&g_cnt[i * 4]) = make_int4(0, 0, 0, 0);
    if (i < 128) g_state[i] = 0;
}

__global__ void hist_rank_kernel(const int* __restrict__ dst, int n_edges)
{
    int t = blockIdx.x * blockDim.x + threadIdx.x;
    int e = t * 4;
    if (e + 3 < n_edges) {
        int4 d = *reinterpret_cast<const int4*>(&dst[e]);
        int r0 = atomicAdd(&g_cnt[d.x], 1);
        int r1 = atomicAdd(&g_cnt[d.y], 1);
        int r2 = atomicAdd(&g_cnt[d.z], 1);
        int r3 = atomicAdd(&g_cnt[d.w], 1);
        *reinterpret_cast<int4*>(&g_rank[e]) = make_int4(r0, r1, r2, r3);
    } else {
        for (; e < n_edges; e++)
            g_rank[e] = atomicAdd(&g_cnt[dst[e]], 1);
    }
}

__global__ void __launch_bounds__(512) scan_onepass_kernel(int n)
{
    __shared__ int wsum[16];
    __shared__ int s_prefix;
    const int b = blockIdx.x;
    const int i = b * 512 + threadIdx.x;
    const int lane = threadIdx.x & 31, wid = threadIdx.x >> 5;

    int v = (i < n) ? g_cnt[i] : 0;
    int x = v;
#pragma unroll
    for (int o = 1; o < 32; o <<= 1) {
        int t = __shfl_up_sync(0xffffffffu, x, o);
        if (lane >= o) x += t;
    }
    if (lane == 31) wsum[wid] = x;
    __syncthreads();
    if (wid == 0) {
        int s = (lane < 16) ? wsum[lane] : 0;
#pragma unroll
        for (int o = 1; o < 16; o <<= 1) {
            int t = __shfl_up_sync(0xffffffffu, s, o);
            if (lane >= o) s += t;
        }
        if (lane < 16) wsum[lane] = s;
    }
    __syncthreads();
    const int base  = (wid > 0) ? wsum[wid - 1] : 0;
    const int total = wsum[15];

    if (threadIdx.x == 0)
        atomicExch(&g_state[b], (total << 2) | (b == 0 ? 2 : 1));

    if (wid == 0) {
        int prefix = 0;
        if (b > 0) {
            int j = b - 1;
            while (true) {
                int idx = j - lane;
                int s = (idx >= 0) ? atomicAdd(&g_state[idx], 0) : 2;
                if (__all_sync(0xffffffffu, (s & 3) != 0)) {
                    unsigned pm = __ballot_sync(0xffffffffu, (s & 3) == 2);
                    int cut = pm ? (__ffs(pm) - 1) : 32;
                    int val = (lane <= cut) ? (s >> 2) : 0;
#pragma unroll
                    for (int o = 16; o; o >>= 1)
                        val += __shfl_xor_sync(0xffffffffu, val, o);
                    prefix += val;
                    if (cut < 32) break;
                    j -= 32;
                }
            }
            if (lane == 0)
                atomicExch(&g_state[b], ((prefix + total) << 2) | 2);
        }
        if (lane == 0) s_prefix = prefix;
    }
    __syncthreads();

    int off = s_prefix + base + x - v;
    if (i < n) g_off[i] = off;
}

__global__ void scatter_kernel(
    const int* __restrict__ src, const int* __restrict__ dst,
    const float* __restrict__ ew, int n_edges)
{
    int t = blockIdx.x * blockDim.x + threadIdx.x;
    int e = t * 4;
    if (e + 3 < n_edges) {
        int4   d = *reinterpret_cast<const int4*>(&dst[e]);
        int4   s = *reinterpret_cast<const int4*>(&src[e]);
        int4   r = *reinterpret_cast<const int4*>(&g_rank[e]);
        float4 w = *reinterpret_cast<const float4*>(&ew[e]);
        int o0 = g_off[d.x], o1 = g_off[d.y], o2 = g_off[d.z], o3 = g_off[d.w];
        g_csr[o0 + r.x] = make_int2(s.x, __float_as_int(w.x));
        g_csr[o1 + r.y] = make_int2(s.y, __float_as_int(w.y));
        g_csr[o2 + r.z] = make_int2(s.z, __float_as_int(w.z));
        g_csr[o3 + r.w] = make_int2(s.w, __float_as_int(w.w));
    } else {
        for (; e < n_edges; e++) {
            int d = dst[e];
            g_csr[g_off[d] + g_rank[e]] = make_int2(src[e], __float_as_int(ew[e]));
        }
    }
}

// ---------------------------------------------------------------------------
// SpMM1 (pull): H[d] = b1 + sum_e w_e * S1[src_e]  — warp per dst.
// Warp = 4 edge-slots x 8 lanes. Lane loads 8 features (uint4, 16B) of its
// slot's edge: ONE gather instruction covers 4 edges (3x fewer mem instrs
// than half2-per-lane). Slots combined by 2 shfl-adds per feature at the end.
// ---------------------------------------------------------------------------
__global__ void __launch_bounds__(256) spmm1_pull_kernel(
    const float* __restrict__ b1, int n_nodes)
{
    const int lane  = threadIdx.x & 31;
    const int lane8 = lane & 7;     // feature group: feats [8*lane8, 8*lane8+8)
    const int slot  = lane >> 3;    // edge slot 0..3
    int d = blockIdx.x * 8 + (threadIdx.x >> 5);
    if (d >= n_nodes) return;

    float acc[8];
#pragma unroll
    for (int f = 0; f < 8; f++) acc[f] = 0.f;

    const int beg = g_off[d];
    const int end = beg + g_cnt[d];

    for (int j = beg; j < end; j += 8) {
        int i0 = j + slot;
        int i1 = j + 4 + slot;
        // inactive slots in the tail read row 0 with weight 0 (harmless)
        int2 e0 = (i0 < end) ? g_csr[i0] : make_int2(0, 0);
        int2 e1 = (i1 < end) ? g_csr[i1] : make_int2(0, 0);
        float w0 = __int_as_float(e0.y);
        float w1 = __int_as_float(e1.y);
        uint4 r0 = *reinterpret_cast<const uint4*>(&g_S1h[e0.x * NHID + lane8 * 8]);
        uint4 r1 = *reinterpret_cast<const uint4*>(&g_S1h[e1.x * NHID + lane8 * 8]);
        const __half2* h0 = reinterpret_cast<const __half2*>(&r0);
        const __half2* h1 = reinterpret_cast<const __half2*>(&r1);
#pragma unroll
        for (int q = 0; q < 4; q++) {
            float2 f0 = __half22float2(h0[q]);
            float2 f1 = __half22float2(h1[q]);
            acc[2 * q + 0] = fmaf(w0, f0.x, acc[2 * q + 0]);
            acc[2 * q + 1] = fmaf(w0, f0.y, acc[2 * q + 1]);
            acc[2 * q + 0] = fmaf(w1, f1.x, acc[2 * q + 0]);
            acc[2 * q + 1] = fmaf(w1, f1.y, acc[2 * q + 1]);
        }
    }

    // combine the 4 edge-slots (lanes with equal lane8 hold the same features)
#pragma unroll
    for (int f = 0; f < 8; f++) {
        acc[f] += __shfl_xor_sync(0xffffffffu, acc[f], 8);
        acc[f] += __shfl_xor_sync(0xffffffffu, acc[f], 16);
    }

    if (slot == 0) {
        const float* bb = &b1[lane8 * 8];
        float4 o0 = make_float4(acc[0] + bb[0], acc[1] + bb[1],
                                acc[2] + bb[2], acc[3] + bb[3]);
        float4 o1 = make_float4(acc[4] + bb[4], acc[5] + bb[5],
                                acc[6] + bb[6], acc[7] + bb[7]);
        *reinterpret_cast<float4*>(&g_H[d * NHID + lane8 * 8])     = o0;
        *reinterpret_cast<float4*>(&g_H[d * NHID + lane8 * 8 + 4]) = o1;
    }
}

// ---------------------------------------------------------------------------
// GEMM2 fused ReLU: S2[N,16] = relu(H)[N,64] @ W2[64,16], fp16 output (R12)
// ---------------------------------------------------------------------------
__global__ void __launch_bounds__(256) gemm2_kernel(
    const float* __restrict__ W2, int n_nodes)
{
    __shared__ float hs[128][68];
    __shared__ float ws2[64][16];

    const int tid = threadIdx.x;
    const int tx = tid & 3;
    const int ty = tid >> 2;
    const int rowBase = blockIdx.x * 128;

#pragma unroll
    for (int j = 0; j < 8; j++) {
        int s = tid + j * 256;
        int r = s >> 4;
        int c4 = s & 15;
        float4 v = make_float4(0.f, 0.f, 0.f, 0.f);
        int grow = rowBase + r;
        if (grow < n_nodes)
            v = *reinterpret_cast<const float4*>(&g_H[grow * NHID + c4 * 4]);
        v.x = fmaxf(v.x, 0.f); v.y = fmaxf(v.y, 0.f);
        v.z = fmaxf(v.z, 0.f); v.w = fmaxf(v.w, 0.f);
        *reinterpret_cast<float4*>(&hs[r][c4 * 4]) = v;
    }
    {
        int kk = tid >> 2;
        int c4 = tid & 3;
        float4 v = *reinterpret_cast<const float4*>(&W2[kk * NCLASS + c4 * 4]);
        *reinterpret_cast<float4*>(&ws2[kk][c4 * 4]) = v;
    }
    __syncthreads();

    float acc0[4] = {0.f, 0.f, 0.f, 0.f};
    float acc1[4] = {0.f, 0.f, 0.f, 0.f};
#pragma unroll
    for (int kk = 0; kk < NHID; kk++) {
        float a0 = hs[ty][kk];
        float a1 = hs[ty + 64][kk];
        float4 w = *reinterpret_cast<const float4*>(&ws2[kk][4 * tx]);
        acc0[0] = fmaf(a0, w.x, acc0[0]); acc0[1] = fmaf(a0, w.y, acc0[1]);
        acc0[2] = fmaf(a0, w.z, acc0[2]); acc0[3] = fmaf(a0, w.w, acc0[3]);
        acc1[0] = fmaf(a1, w.x, acc1[0]); acc1[1] = fmaf(a1, w.y, acc1[1]);
        acc1[2] = fmaf(a1, w.z, acc1[2]); acc1[3] = fmaf(a1, w.w, acc1[3]);
    }

    int r0 = rowBase + ty, r1 = rowBase + ty + 64;
    if (r0 < n_nodes) {
        __half2 h2[2] = { __floats2half2_rn(acc0[0], acc0[1]),
                          __floats2half2_rn(acc0[2], acc0[3]) };
        *reinterpret_cast<uint2*>(&g_S2h[r0 * NCLASS + 4 * tx]) =
            *reinterpret_cast<const uint2*>(h2);
    }
    if (r1 < n_nodes) {
        __half2 h2[2] = { __floats2half2_rn(acc1[0], acc1[1]),
                          __floats2half2_rn(acc1[2], acc1[3]) };
        *reinterpret_cast<uint2*>(&g_S2h[r1 * NCLASS + 4 * tx]) =
            *reinterpret_cast<const uint2*>(h2);
    }
}

// ---------------------------------------------------------------------------
// SpMM2 (pull) + bias + log_softmax fused (R12 exact: 4-edge unroll)
// ---------------------------------------------------------------------------
__global__ void __launch_bounds__(256) spmm2_lsm_kernel(
    const float* __restrict__ b2, float* __restrict__ out, int n_nodes)
{
    int lane16 = threadIdx.x & 15;
    int d = blockIdx.x * 16 + (threadIdx.x >> 4);
    if (d >= n_nodes) return;

    float acc = b2[lane16];
    int beg = g_off[d];
    int end = beg + g_cnt[d];
    int j = beg;

    if ((j & 1) && j < end) {
        int2 e = g_csr[j];
        acc = fmaf(__int_as_float(e.y), __half2float(g_S2h[e.x * NCLASS + lane16]), acc);
        j++;
    }
    const int4* csr4 = reinterpret_cast<const int4*>(g_csr);
    for (; j + 3 < end; j += 4) {
        int h = j >> 1;
        int4 p0 = csr4[h], p1 = csr4[h + 1];
        float v0 = __half2float(g_S2h[p0.x * NCLASS + lane16]);
        float v1 = __half2float(g_S2h[p0.z * NCLASS + lane16]);
        float v2 = __half2float(g_S2h[p1.x * NCLASS + lane16]);
        float v3 = __half2float(g_S2h[p1.z * NCLASS + lane16]);
        acc = fmaf(__int_as_float(p0.y), v0, acc);
        acc = fmaf(__int_as_float(p0.w), v1, acc);
        acc = fmaf(__int_as_float(p1.y), v2, acc);
        acc = fmaf(__int_as_float(p1.w), v3, acc);
    }
    for (; j < end; j++) {
        int2 e = g_csr[j];
        acc = fmaf(__int_as_float(e.y), __half2float(g_S2h[e.x * NCLASS + lane16]), acc);
    }

    float m = acc;
#pragma unroll
    for (int o = 8; o >= 1; o >>= 1)
        m = fmaxf(m, __shfl_xor_sync(0xffffffffu, m, o, 16));
    float ssum = expf(acc - m);
#pragma unroll
    for (int o = 8; o >= 1; o >>= 1)
        ssum += __shfl_xor_sync(0xffffffffu, ssum, o, 16);
    out[d * NCLASS + lane16] = acc - m - logf(ssum);
}

// ---------------------------------------------------------------------------
// Launch.  Inputs: x, W1, b1, W2, b2, edge_src, edge_dst, edge_weight
// gemm1 forks onto a side stream, overlapping the CSR build; joins before spmm1.
// ---------------------------------------------------------------------------
extern "C" void kernel_launch(void* const* d_in, const int* in_sizes, int n_in,
                              void* d_out, int out_size)
{
    const float* x    = (const float*)d_in[0];
    const float* W1   = (const float*)d_in[1];
    const float* b1   = (const float*)d_in[2];
    const float* W2   = (const float*)d_in[3];
    const float* b2   = (const float*)d_in[4];
    const int*   esrc = (const int*)d_in[5];
    const int*   edst = (const int*)d_in[6];
    const float* ew   = (const float*)d_in[7];

    int n_nodes = in_sizes[0] / NFEAT;
    int n_edges = in_sizes[5];
    int nb  = (n_nodes + 511) / 512;
    int n4e = (n_edges + 3) / 4;
    int n4n = (n_nodes + 3) / 4;

    cudaStream_t s1;
    cudaEvent_t evFork, evJoin;
    cudaStreamCreateWithFlags(&s1, cudaStreamNonBlocking);
    cudaEventCreateWithFlags(&evFork, cudaEventDisableTiming);
    cudaEventCreateWithFlags(&evJoin, cudaEventDisableTiming);

    cudaEventRecord(evFork, 0);
    cudaStreamWaitEvent(s1, evFork, 0);
    gemm1_tf32_kernel<<<(n_nodes + 63) / 64, 256, 0, s1>>>(x, W1, n_nodes);
    cudaEventRecord(evJoin, s1);

    // CSR-by-dst build (default stream) — exact R12 config
    zero_cnt_kernel<<<(n4n + 255) / 256, 256>>>(n4n);
    hist_rank_kernel<<<(n4e + 255) / 256, 256>>>(edst, n_edges);
    scan_onepass_kernel<<<nb, 512>>>(n_nodes);
    scatter_kernel<<<(n4e + 255) / 256, 256>>>(esrc, edst, ew, n_edges);

    cudaStreamWaitEvent(0, evJoin, 0);

    // Layer 1 aggregate: warp per dst, 4-edge-wide gathers
    spmm1_pull_kernel<<<(n_nodes + 7) / 8, 256>>>(b1, n_nodes);
    gemm2_kernel<<<(n_nodes + 127) / 128, 256>>>(W2, n_nodes);
    spmm2_lsm_kernel<<<(n_nodes + 15) / 16, 256>>>(b2, (float*)d_out, n_nodes);

    cudaEventDestroy(evFork);
    cudaEventDestroy(evJoin);
    cudaStreamDestroy(s1);
}